// round 3
// baseline (speedup 1.0000x reference)
#include <cuda_runtime.h>

#define BATCH 1024
#define FEAT 256
#define NUM_CLASSES 100000
#define CLAMP_MIN 1e-12f
#define CLAMP_MAX 1e12f
#define WARPS_PER_BLOCK 16
#define ROWS_PER_BLOCK WARPS_PER_BLOCK
#define NUM_BLOCKS (BATCH / ROWS_PER_BLOCK)   // 64

// Scratch for single-kernel cross-block reduction (no device mallocs allowed).
__device__ float    g_partial[NUM_BLOCKS];
__device__ unsigned g_count = 0;   // zero at module load; reset by last block each run

__global__ __launch_bounds__(WARPS_PER_BLOCK * 32)
void center_loss_kernel(const float* __restrict__ x,
                        const float* __restrict__ centers,
                        const int* __restrict__ labels,   // JAX x64 disabled -> int32
                        float* __restrict__ out) {
    const int warp = threadIdx.x >> 5;
    const int lane = threadIdx.x & 31;
    const int row  = blockIdx.x * ROWS_PER_BLOCK + warp;

    int lbl = __ldg(&labels[row]);
    lbl = min(max(lbl, 0), NUM_CLASSES - 1);   // defensive, branch-free

    const float4* xr = reinterpret_cast<const float4*>(x + (size_t)row * FEAT);
    const float4* cr = reinterpret_cast<const float4*>(centers + (size_t)lbl * FEAT);

    // 256 floats = 64 float4 per row; 32 lanes * 2 float4 each. 4 independent
    // 16B loads per lane -> all in flight before the dependent math.
    float p = 0.0f;
    #pragma unroll
    for (int i = 0; i < 2; i++) {
        float4 a = xr[lane + i * 32];
        float4 b = cr[lane + i * 32];
        float sx  = a.x * a.x + a.y * a.y + a.z * a.z + a.w * a.w;
        float sc  = b.x * b.x + b.y * b.y + b.z * b.z + b.w * b.w;
        float sxc = a.x * b.x + a.y * b.y + a.z * b.z + a.w * b.w;
        p += sx + sc - 2.0f * sxc;
    }

    // warp reduction
    #pragma unroll
    for (int off = 16; off > 0; off >>= 1)
        p += __shfl_xor_sync(0xFFFFFFFFu, p, off);

    __shared__ float bs[WARPS_PER_BLOCK];
    __shared__ bool  is_last;
    if (lane == 0)
        bs[warp] = fminf(fmaxf(p, CLAMP_MIN), CLAMP_MAX);
    __syncthreads();

    // Block partial (deterministic order), published to global scratch.
    if (threadIdx.x == 0) {
        float s = 0.0f;
        #pragma unroll
        for (int w = 0; w < WARPS_PER_BLOCK; w++) s += bs[w];
        g_partial[blockIdx.x] = s;
        __threadfence();                         // make partial visible before ticket
        unsigned old = atomicAdd(&g_count, 1u);
        is_last = (old == NUM_BLOCKS - 1);
    }
    __syncthreads();

    // Last-arriving block: warp 0 reduces the 64 partials, fixed order.
    if (is_last && warp == 0) {
        float v = g_partial[lane] + g_partial[lane + 32];
        #pragma unroll
        for (int off = 16; off > 0; off >>= 1)
            v += __shfl_xor_sync(0xFFFFFFFFu, v, off);
        if (lane == 0) {
            *out = v * (1.0f / BATCH)
                 + (float)((double)(NUM_CLASSES - 1) * 1e-12);
            g_count = 0;                         // re-arm for next graph replay
        }
    }
}

extern "C" void kernel_launch(void* const* d_in, const int* in_sizes, int n_in,
                              void* d_out, int out_size) {
    // Resolve inputs by element count:
    //   x: 1024*256 = 262144, centers: 100000*256 = 25600000, labels: 1024
    const float* x = nullptr;
    const float* centers = nullptr;
    const int*   labels = nullptr;
    for (int i = 0; i < n_in; i++) {
        if (in_sizes[i] == BATCH * FEAT)            x       = (const float*)d_in[i];
        else if (in_sizes[i] == NUM_CLASSES * FEAT) centers = (const float*)d_in[i];
        else                                        labels  = (const int*)d_in[i];
    }
    center_loss_kernel<<<NUM_BLOCKS, WARPS_PER_BLOCK * 32>>>(
        x, centers, labels, (float*)d_out);
}

// round 5
// speedup vs baseline: 1.0337x; 1.0337x over previous
#include <cuda_runtime.h>

#define BATCH 1024
#define FEAT 256
#define NUM_CLASSES 100000
#define CLAMP_MIN 1e-12f
#define CLAMP_MAX 1e12f
#define WARPS_PER_BLOCK 8
#define ROWS_PER_BLOCK WARPS_PER_BLOCK
#define NUM_BLOCKS (BATCH / ROWS_PER_BLOCK)   // 128 blocks -> one wave on 148+ SMs

// Cross-block reduction scratch (zero at module load; re-armed by last block).
__device__ float    g_acc   = 0.0f;
__device__ unsigned g_count = 0;

__global__ __launch_bounds__(WARPS_PER_BLOCK * 32)
void center_loss_kernel(const float* __restrict__ x,
                        const float* __restrict__ centers,
                        const int* __restrict__ labels,   // JAX x64 disabled -> int32
                        float* __restrict__ out) {
    const int warp = threadIdx.x >> 5;
    const int lane = threadIdx.x & 31;
    const int row  = blockIdx.x * ROWS_PER_BLOCK + warp;

    // Label load starts the dependent gather chain immediately.
    int lbl = __ldg(&labels[row]);
    lbl = min(max(lbl, 0), NUM_CLASSES - 1);   // defensive, branch-free

    const float4* xr = reinterpret_cast<const float4*>(x + (size_t)row * FEAT);
    const float4* cr = reinterpret_cast<const float4*>(centers + (size_t)lbl * FEAT);

    // x loads are independent of the label -> in flight during the label wait.
    float4 a0 = xr[lane];
    float4 a1 = xr[lane + 32];
    float sx = a0.x*a0.x + a0.y*a0.y + a0.z*a0.z + a0.w*a0.w
             + a1.x*a1.x + a1.y*a1.y + a1.z*a1.z + a1.w*a1.w;

    float4 b0 = cr[lane];
    float4 b1 = cr[lane + 32];
    float sc  = b0.x*b0.x + b0.y*b0.y + b0.z*b0.z + b0.w*b0.w
              + b1.x*b1.x + b1.y*b1.y + b1.z*b1.z + b1.w*b1.w;
    float sxc = a0.x*b0.x + a0.y*b0.y + a0.z*b0.z + a0.w*b0.w
              + a1.x*b1.x + a1.y*b1.y + a1.z*b1.z + a1.w*b1.w;

    float p = sx + sc - 2.0f * sxc;

    // Warp reduction (redux.sync.add.f32 not admitted on plain sm_103 target).
    #pragma unroll
    for (int off = 16; off > 0; off >>= 1)
        p += __shfl_xor_sync(0xFFFFFFFFu, p, off);

    __shared__ float bs[WARPS_PER_BLOCK];
    if (lane == 0)
        bs[warp] = fminf(fmaxf(p, CLAMP_MIN), CLAMP_MAX);
    __syncthreads();

    if (threadIdx.x == 0) {
        float s = 0.0f;
        #pragma unroll
        for (int w = 0; w < WARPS_PER_BLOCK; w++) s += bs[w];

        // Publish into a single accumulator, then take a ticket. The fence
        // orders this block's acc-add before its ticket, so when a block sees
        // ticket == NUM_BLOCKS-1, all acc-adds have committed at L2.
        atomicAdd(&g_acc, s);
        __threadfence();
        unsigned c = atomicAdd(&g_count, 1u);
        if (c == NUM_BLOCKS - 1) {
            float tot = atomicAdd(&g_acc, 0.0f);   // L2 RMW read of the total
            *out = tot * (1.0f / BATCH)
                 + (float)((double)(NUM_CLASSES - 1) * 1e-12);
            // Re-arm for the next graph replay (kernel-exit flush publishes).
            g_acc   = 0.0f;
            g_count = 0;
        }
    }
}

extern "C" void kernel_launch(void* const* d_in, const int* in_sizes, int n_in,
                              void* d_out, int out_size) {
    // Resolve inputs by element count:
    //   x: 1024*256 = 262144, centers: 100000*256 = 25600000, labels: 1024
    const float* x = nullptr;
    const float* centers = nullptr;
    const int*   labels = nullptr;
    for (int i = 0; i < n_in; i++) {
        if (in_sizes[i] == BATCH * FEAT)            x       = (const float*)d_in[i];
        else if (in_sizes[i] == NUM_CLASSES * FEAT) centers = (const float*)d_in[i];
        else                                        labels  = (const int*)d_in[i];
    }
    center_loss_kernel<<<NUM_BLOCKS, WARPS_PER_BLOCK * 32>>>(
        x, centers, labels, (float*)d_out);
}

// round 6
// speedup vs baseline: 1.0386x; 1.0048x over previous
#include <cuda_runtime.h>

#define BATCH 1024
#define FEAT 256
#define NUM_CLASSES 100000
#define CLAMP_MIN 1e-12f
#define CLAMP_MAX 1e12f
#define THREADS_PER_BLOCK 1024
#define WARPS_PER_BLOCK 32
#define ROWS_PER_BLOCK WARPS_PER_BLOCK
#define NUM_BLOCKS (BATCH / ROWS_PER_BLOCK)   // 32 blocks -> short atomic chains

// Cross-block reduction scratch (zero at module load; re-armed by last block).
__device__ float    g_acc   = 0.0f;
__device__ unsigned g_count = 0;

__global__ __launch_bounds__(THREADS_PER_BLOCK)
void center_loss_kernel(const float* __restrict__ x,
                        const float* __restrict__ centers,
                        const int* __restrict__ labels,   // JAX x64 disabled -> int32
                        float* __restrict__ out) {
    const int warp = threadIdx.x >> 5;
    const int lane = threadIdx.x & 31;
    const int row  = blockIdx.x * ROWS_PER_BLOCK + warp;

    // Label load starts the dependent gather chain immediately.
    int lbl = __ldg(&labels[row]);
    lbl = min(max(lbl, 0), NUM_CLASSES - 1);   // defensive, branch-free

    const float4* xr = reinterpret_cast<const float4*>(x + (size_t)row * FEAT);
    const float4* cr = reinterpret_cast<const float4*>(centers + (size_t)lbl * FEAT);

    // x loads are independent of the label -> in flight during the label wait.
    float4 a0 = xr[lane];
    float4 a1 = xr[lane + 32];
    float sx = a0.x*a0.x + a0.y*a0.y + a0.z*a0.z + a0.w*a0.w
             + a1.x*a1.x + a1.y*a1.y + a1.z*a1.z + a1.w*a1.w;

    float4 b0 = cr[lane];
    float4 b1 = cr[lane + 32];
    float sc  = b0.x*b0.x + b0.y*b0.y + b0.z*b0.z + b0.w*b0.w
              + b1.x*b1.x + b1.y*b1.y + b1.z*b1.z + b1.w*b1.w;
    float sxc = a0.x*b0.x + a0.y*b0.y + a0.z*b0.z + a0.w*b0.w
              + a1.x*b1.x + a1.y*b1.y + a1.z*b1.z + a1.w*b1.w;

    float p = sx + sc - 2.0f * sxc;

    // Warp reduction (f32 redux not admitted on plain sm_103 target).
    #pragma unroll
    for (int off = 16; off > 0; off >>= 1)
        p += __shfl_xor_sync(0xFFFFFFFFu, p, off);

    __shared__ float bs[WARPS_PER_BLOCK];
    if (lane == 0)
        bs[warp] = fminf(fmaxf(p, CLAMP_MIN), CLAMP_MAX);
    __syncthreads();

    // Warp 0 reduces the 32 warp partials (parallel, not a serial 32-add loop).
    if (warp == 0) {
        float s = bs[lane];
        #pragma unroll
        for (int off = 16; off > 0; off >>= 1)
            s += __shfl_xor_sync(0xFFFFFFFFu, s, off);

        if (lane == 0) {
            // Publish this block's sum (relaxed device RMW, 32-deep chain).
            atomicAdd(&g_acc, s);

            // Acq-rel ticket subsumes the __threadfence: the release makes our
            // g_acc add visible; the acquire side of the RMW that reads the
            // final count synchronizes with the whole release sequence, so all
            // 32 g_acc adds are visible to the last block.
            unsigned c;
            asm volatile("atom.acq_rel.gpu.add.u32 %0, [%1], %2;"
                         : "=r"(c) : "l"(&g_count), "r"(1u) : "memory");

            if (c == NUM_BLOCKS - 1) {
                float tot;
                asm volatile("ld.global.f32 %0, [%1];"
                             : "=f"(tot) : "l"(&g_acc) : "memory");
                *out = tot * (1.0f / BATCH)
                     + (float)((double)(NUM_CLASSES - 1) * 1e-12);
                // Re-arm for the next graph replay (kernel-exit flush publishes).
                g_acc   = 0.0f;
                g_count = 0;
            }
        }
    }
}

extern "C" void kernel_launch(void* const* d_in, const int* in_sizes, int n_in,
                              void* d_out, int out_size) {
    // Resolve inputs by element count:
    //   x: 1024*256 = 262144, centers: 100000*256 = 25600000, labels: 1024
    const float* x = nullptr;
    const float* centers = nullptr;
    const int*   labels = nullptr;
    for (int i = 0; i < n_in; i++) {
        if (in_sizes[i] == BATCH * FEAT)            x       = (const float*)d_in[i];
        else if (in_sizes[i] == NUM_CLASSES * FEAT) centers = (const float*)d_in[i];
        else                                        labels  = (const int*)d_in[i];
    }
    center_loss_kernel<<<NUM_BLOCKS, THREADS_PER_BLOCK>>>(
        x, centers, labels, (float*)d_out);
}